// round 4
// baseline (speedup 1.0000x reference)
#include <cuda_runtime.h>

#define LOG2E 1.4426950408889634f
#define LN2   0.6931471805599453f

__device__ float g_partial[1024];
__device__ int   g_perm[1024];
__device__ unsigned int g_count = 0;

static __device__ __forceinline__ float ex2f_(float x) {
    float y; asm("ex2.approx.ftz.f32 %0, %1;" : "=f"(y) : "f"(x)); return y;
}
static __device__ __forceinline__ float lg2f_(float x) {
    float y; asm("lg2.approx.ftz.f32 %0, %1;" : "=f"(y) : "f"(x)); return y;
}
static __device__ __forceinline__ unsigned long long pack2_(float lo, float hi) {
    unsigned long long d;
    asm("mov.b64 %0, {%1, %2};" : "=l"(d) : "f"(lo), "f"(hi));
    return d;
}
static __device__ __forceinline__ unsigned long long fma2_(unsigned long long a,
                                                           unsigned long long b,
                                                           unsigned long long c) {
    unsigned long long d;
    asm("fma.rn.f32x2 %0, %1, %2, %3;" : "=l"(d) : "l"(a), "l"(b), "l"(c));
    return d;
}
static __device__ __forceinline__ unsigned long long addx2_(unsigned long long a,
                                                            unsigned long long b) {
    unsigned long long d;
    asm("add.rn.f32x2 %0, %1, %2;" : "=l"(d) : "l"(a), "l"(b));
    return d;
}
static __device__ __forceinline__ void unpack2_(unsigned long long v, float& lo, float& hi) {
    asm("mov.b64 {%0, %1}, %2;" : "=f"(lo), "=f"(hi) : "l"(v));
}

// 32-MAC half-contraction + pair combine. CUR literal, WB an array name, SVAR output.
#define MACS2(CUR, WB, SVAR)                                                \
    {                                                                       \
        const ulonglong2* wv_ = (const ulonglong2*)(&WB[CUR][0] + 40 * h);  \
        unsigned long long a0_ = 0ull, a1_ = 0ull, a2_ = 0ull, a3_ = 0ull;  \
        _Pragma("unroll")                                                   \
        for (int k_ = 0; k_ < 8; k_ += 2) {                                 \
            ulonglong2 q0_ = wv_[k_];                                       \
            ulonglong2 q1_ = wv_[k_ + 1];                                   \
            a0_ = fma2_(q0_.x, e2[2 * k_ + 0], a0_);                        \
            a1_ = fma2_(q0_.y, e2[2 * k_ + 1], a1_);                        \
            a2_ = fma2_(q1_.x, e2[2 * k_ + 2], a2_);                        \
            a3_ = fma2_(q1_.y, e2[2 * k_ + 3], a3_);                        \
        }                                                                   \
        float lo_, hi_;                                                     \
        unpack2_(addx2_(addx2_(a0_, a2_), addx2_(a1_, a3_)), lo_, hi_);     \
        float part_ = lo_ + hi_;                                            \
        SVAR = part_ + __shfl_xor_sync(0xffffffffu, part_, 1);              \
    }

// Superstep: one recurrence step for BOTH batches, one barrier.
#define SSTEP(UU, CUR, NORM)                                                \
    {                                                                       \
        float p0_, p1_;                                                     \
        if (NORM) {                                                         \
            float D0_ = scal0[CUR]; float lD0_ = lg2f_(D0_); loff0 += lD0_; \
            p0_ = ex2f_(fmaf(pf0[UU], LOG2E, -lD0_));                       \
            float D1_ = scal1[CUR]; float lD1_ = lg2f_(D1_); loff1 += lD1_; \
            p1_ = ex2f_(fmaf(pf1[UU], LOG2E, -lD1_));                       \
        } else {                                                            \
            p0_ = ex2f_(pf0[UU] * LOG2E);                                   \
            p1_ = ex2f_(pf1[UU] * LOG2E);                                   \
        }                                                                   \
        pf0[UU] = *(const float*)(potc0 + off0);                            \
        off0 = min(off0 + 256, offmax0);                                    \
        pf1[UU] = *(const float*)(potc1 + off1);                            \
        off1 = min(off1 + 256, offmax1);                                    \
        float s0_, s1_;                                                     \
        MACS2(CUR, wb0, s0_)                                                \
        MACS2(CUR, wb1, s1_)                                                \
        float v0_ = s0_ * p0_;                                              \
        float v1_ = s1_ * p1_;                                              \
        if (h == 0) { wb0[(CUR) ^ 1][wslot] = v0_;                          \
                      wb1[(CUR) ^ 1][wslot] = v1_; }                        \
        if (tid == 0) { scal0[(CUR) ^ 1] = v0_;                            \
                        scal1[(CUR) ^ 1] = v1_; }                          \
        __syncthreads();                                                    \
    }

// Tail step: batch0 only (the longer one).
#define TSTEP(QQ, CUR, NORM)                                                \
    {                                                                       \
        float p0_;                                                          \
        if (NORM) {                                                         \
            float D_ = scal0[CUR]; float lD_ = lg2f_(D_); loff0 += lD_;     \
            p0_ = ex2f_(fmaf(tq[QQ], LOG2E, -lD_));                         \
        } else {                                                            \
            p0_ = ex2f_(tq[QQ] * LOG2E);                                    \
        }                                                                   \
        tq[QQ] = *(const float*)(potc0 + offT);                             \
        offT = min(offT + 256, offmax0);                                    \
        float s0_;                                                          \
        MACS2(CUR, wb0, s0_)                                                \
        float v0_ = s0_ * p0_;                                              \
        if (h == 0) wb0[(CUR) ^ 1][wslot] = v0_;                            \
        if (tid == 0) scal0[(CUR) ^ 1] = v0_;                               \
        __syncthreads();                                                    \
    }

// Bitonic sort of sequence lengths (ascending); writes permutation to g_perm.
__global__ void sort_len_kernel(const int* __restrict__ seqlen, int B, int T) {
    __shared__ int key[1024];
    __shared__ int idxs[1024];
    int n = blockDim.x;
    int tid = threadIdx.x;
    int v = -1;
    if (tid < B) {
        v = seqlen[tid];
        if (v > T) v = T;
        if (v < 1) v = 1;
    }
    key[tid] = v;
    idxs[tid] = tid;
    __syncthreads();
    for (int k = 2; k <= n; k <<= 1) {
        for (int jj = k >> 1; jj > 0; jj >>= 1) {
            int ixj = tid ^ jj;
            if (ixj > tid) {
                bool up = ((tid & k) == 0);
                int ka = key[tid], kb = key[ixj];
                bool sw = up ? (ka > kb) : (ka < kb);
                if (sw) {
                    key[tid] = kb; key[ixj] = ka;
                    int t_ = idxs[tid]; idxs[tid] = idxs[ixj]; idxs[ixj] = t_;
                }
            }
            __syncthreads();
        }
    }
    if (tid < B) g_perm[tid] = idxs[tid];
}

// One CTA per PAIR of batches. 128 threads: (j = tid>>1, h = tid&1).
__global__ __launch_bounds__(128, 1) void crf_scan2_kernel(
    const float* __restrict__ pot,     // [B, T, 64]
    const int*   __restrict__ tags,    // [B, T]
    const int*   __restrict__ seqlen,  // [B]
    const float* __restrict__ K,       // [64, 64]
    const float* __restrict__ sw,      // [B]
    float*       __restrict__ out,
    int T, int B)
{
    const int tid = threadIdx.x;
    const int j   = tid >> 1;
    const int h   = tid & 1;

    __shared__ __align__(16) float wb0[2][80];
    __shared__ __align__(16) float wb1[2][80];
    __shared__ float scal0[2], scal1[2];
    __shared__ float sred0[128], sred1[128];
    __shared__ int   stags0[1024], stags1[1024];

    int b0i = 2 * blockIdx.x;
    int b1i = b0i + 1 < B ? b0i + 1 : b0i;
    int b0 = g_perm[b0i];
    int b1 = g_perm[b1i];

    int L0 = seqlen[b0]; if (L0 > T) L0 = T; if (L0 < 1) L0 = 1;
    int L1 = seqlen[b1]; if (L1 > T) L1 = T; if (L1 < 1) L1 = 1;
    if (L1 > L0) { int t_ = b0; b0 = b1; b1 = t_; t_ = L0; L0 = L1; L1 = t_; }

    const float* potb0 = pot  + (size_t)b0 * T * 64;
    const float* potb1 = pot  + (size_t)b1 * T * 64;
    const int*   tagb0 = tags + (size_t)b0 * T;
    const int*   tagb1 = tags + (size_t)b1 * T;

    // ---- stage tags (T assumed <= 1024 for this problem) ----
    for (int t = tid; t < T; t += 128) {
        stags0[t] = tagb0[t];
        stags1[t] = tagb1[t];
    }
    __syncthreads();

    // ---- sequence-score gathers, both batches ----
    float acc0 = 0.f, acc1 = 0.f;
    for (int t = tid; t < T; t += 128) {
        if (t < L0) {
            int tg = stags0[t];
            acc0 += __ldg(potb0 + (size_t)t * 64 + tg);
            if (t >= 1) acc0 += __ldg(K + stags0[t - 1] * 64 + tg);
        }
        if (t < L1) {
            int tg = stags1[t];
            acc1 += __ldg(potb1 + (size_t)t * 64 + tg);
            if (t >= 1) acc1 += __ldg(K + stags1[t - 1] * 64 + tg);
        }
    }
    sred0[tid] = acc0;
    sred1[tid] = acc1;

    // ---- E block (shared by both batches): i-range [32h, 32h+32) ----
    unsigned long long e2[16];
#pragma unroll
    for (int m = 0; m < 16; m++) {
        int i0 = 32 * h + 2 * m;
        e2[m] = pack2_(ex2f_(K[i0 * 64 + j] * LOG2E),
                       ex2f_(K[(i0 + 1) * 64 + j] * LOG2E));
    }

    const int wslot = (j < 32) ? j : (40 + j - 32);

    // ---- init w(0) for both ----
    if (h == 0) {
        float v00 = ex2f_(potb0[j] * LOG2E);
        float v01 = ex2f_(potb1[j] * LOG2E);
        wb0[0][wslot] = v00;
        wb1[0][wslot] = v01;
        if (j == 0) { scal0[0] = v00; scal1[0] = v01; }
    }
    __syncthreads();

    // ---- prefetch rings ----
    const char* potc0 = (const char*)potb0;
    const char* potc1 = (const char*)potb1;
    const int offmax0 = (T - 1) * 256 + (j << 2);
    const int offmax1 = offmax0;  // same layout
    float pf0[4], pf1[4];
#pragma unroll
    for (int u = 0; u < 4; u++) {
        int row = 1 + u; if (row > T - 1) row = T - 1;
        pf0[u] = potb0[(size_t)row * 64 + j];
        pf1[u] = potb1[(size_t)row * 64 + j];
    }
    int off0 = 5 * 256 + (j << 2); if (off0 > offmax0) off0 = offmax0;
    int off1 = off0;

    float loff0 = 0.f, loff1 = 0.f;

    // ---- common phase: nc = L1-1 supersteps (both batches) ----
    const int nc = L1 - 1;
    int n4 = nc >> 2;
    for (int it = 0; it < n4; it++) {
        SSTEP(0, 0, 1) SSTEP(1, 1, 0) SSTEP(2, 0, 1) SSTEP(3, 1, 0)
    }
    const int remc = nc & 3;
    if (remc > 0) SSTEP(0, 0, 1)
    if (remc > 1) SSTEP(1, 1, 0)
    if (remc > 2) SSTEP(2, 0, 1)

    // ---- tail: batch0 alone for nt = L0-L1 steps ----
    const int nt = L0 - L1;
    if (nt > 0) {
        float tq[4];
#pragma unroll
        for (int u = 0; u < 4; u++) {
            int r = L1 + u; if (r > T - 1) r = T - 1;
            tq[u] = *(const float*)(potc0 + (size_t)r * 256 + (j << 2));
        }
        int rT = L1 + 4; if (rT > T - 1) rT = T - 1;
        int offT = rT * 256 + (j << 2);

        int nt4 = nt >> 2;
        int ntr = nt & 3;
        if ((nc & 1) == 0) {
            for (int it = 0; it < nt4; it++) {
                TSTEP(0, 0, 1) TSTEP(1, 1, 0) TSTEP(2, 0, 1) TSTEP(3, 1, 0)
            }
            if (ntr > 0) TSTEP(0, 0, 1)
            if (ntr > 1) TSTEP(1, 1, 0)
            if (ntr > 2) TSTEP(2, 0, 1)
        } else {
            for (int it = 0; it < nt4; it++) {
                TSTEP(0, 1, 1) TSTEP(1, 0, 0) TSTEP(2, 1, 1) TSTEP(3, 0, 0)
            }
            if (ntr > 0) TSTEP(0, 1, 1)
            if (ntr > 1) TSTEP(1, 0, 0)
            if (ntr > 2) TSTEP(2, 1, 1)
        }
    }

    // ---- finalize both batches + fused global reduction ----
    if (tid == 0) {
        const int fin0 = (L0 - 1) & 1;
        const int fin1 = (L1 - 1) & 1;
        float sum0 = 0.f, sum1 = 0.f;
#pragma unroll
        for (int i = 0; i < 32; i++) { sum0 += wb0[fin0][i];      sum1 += wb1[fin1][i]; }
#pragma unroll
        for (int i = 0; i < 32; i++) { sum0 += wb0[fin0][40 + i]; sum1 += wb1[fin1][40 + i]; }
        float seqs0 = 0.f, seqs1 = 0.f;
#pragma unroll
        for (int i = 0; i < 128; i++) { seqs0 += sred0[i]; seqs1 += sred1[i]; }
        float ln0 = (loff0 + lg2f_(sum0)) * LN2;
        float ln1 = (loff1 + lg2f_(sum1)) * LN2;
        g_partial[b0] = -(seqs0 - ln0) * sw[b0];
        g_partial[b1] = -(seqs1 - ln1) * sw[b1];
        __threadfence();
        unsigned int old = atomicAdd(&g_count, 1);
        if (old == gridDim.x - 1) {
            g_count = 0;               // reset for next graph replay
            __threadfence();
            float tot = 0.f;
#pragma unroll 8
            for (int i = 0; i < B; i++) tot += g_partial[i];
            *out = tot / (float)B;
        }
    }
}

extern "C" void kernel_launch(void* const* d_in, const int* in_sizes, int n_in,
                              void* d_out, int out_size) {
    const float* pot    = (const float*)d_in[0];
    const int*   tags   = (const int*)d_in[1];
    const int*   seqlen = (const int*)d_in[2];
    const float* K      = (const float*)d_in[3];
    const float* sw     = (const float*)d_in[4];

    int B = in_sizes[2];            // sequence_length element count
    int T = in_sizes[1] / B;        // tags is [B, T]

    int n = 1; while (n < B) n <<= 1;
    if (n > 1024) n = 1024;
    sort_len_kernel<<<1, n>>>(seqlen, B, T);

    int pairs = (B + 1) / 2;
    crf_scan2_kernel<<<pairs, 128>>>(pot, tags, seqlen, K, sw, (float*)d_out, T, B);
}

// round 5
// speedup vs baseline: 3.2711x; 3.2711x over previous
#include <cuda_runtime.h>

#define LOG2E 1.4426950408889634f
#define LN2   0.6931471805599453f
#define CHUNK 256
#define NTASK 7          // slots 0..3 = q_1..q_4 (backward), 4..6 = r_1..r_3 (forward)

__device__ float g_vec[1024][NTASK][64];
__device__ float g_loff[1024][NTASK];
__device__ float g_partial[1024];
__device__ unsigned int g_count = 0;

static __device__ __forceinline__ float ex2f_(float x) {
    float y; asm("ex2.approx.ftz.f32 %0, %1;" : "=f"(y) : "f"(x)); return y;
}
static __device__ __forceinline__ float lg2f_(float x) {
    float y; asm("lg2.approx.ftz.f32 %0, %1;" : "=f"(y) : "f"(x)); return y;
}
static __device__ __forceinline__ unsigned long long pack2_(float lo, float hi) {
    unsigned long long d;
    asm("mov.b64 %0, {%1, %2};" : "=l"(d) : "f"(lo), "f"(hi));
    return d;
}
static __device__ __forceinline__ unsigned long long fma2_(unsigned long long a,
                                                           unsigned long long b,
                                                           unsigned long long c) {
    unsigned long long d;
    asm("fma.rn.f32x2 %0, %1, %2, %3;" : "=l"(d) : "l"(a), "l"(b), "l"(c));
    return d;
}
static __device__ __forceinline__ unsigned long long addx2_(unsigned long long a,
                                                            unsigned long long b) {
    unsigned long long d;
    asm("add.rn.f32x2 %0, %1, %2;" : "=l"(d) : "l"(a), "l"(b));
    return d;
}
static __device__ __forceinline__ void unpack2_(unsigned long long v, float& lo, float& hi) {
    asm("mov.b64 {%0, %1}, %2;" : "=f"(lo), "=f"(hi) : "l"(v));
}

// s = sum_m e2[m] * BUF[2m..2m+1]  (64 MACs as 32 packed FFMA2, broadcast LDS)
#define MAC64(BUF, SVAR)                                                    \
    {                                                                       \
        const ulonglong2* wv_ = (const ulonglong2*)(BUF);                   \
        unsigned long long a0_ = 0ull, a1_ = 0ull, a2_ = 0ull, a3_ = 0ull;  \
        _Pragma("unroll")                                                   \
        for (int k_ = 0; k_ < 8; k_++) {                                    \
            ulonglong2 q0_ = wv_[2 * k_];                                   \
            ulonglong2 q1_ = wv_[2 * k_ + 1];                               \
            a0_ = fma2_(q0_.x, e2[4 * k_ + 0], a0_);                        \
            a1_ = fma2_(q0_.y, e2[4 * k_ + 1], a1_);                        \
            a2_ = fma2_(q1_.x, e2[4 * k_ + 2], a2_);                        \
            a3_ = fma2_(q1_.y, e2[4 * k_ + 3], a3_);                        \
        }                                                                   \
        float lo_, hi_;                                                     \
        unpack2_(addx2_(addx2_(a0_, a2_), addx2_(a1_, a3_)), lo_, hi_);     \
        SVAR = lo_ + hi_;                                                   \
    }

// forward:  alpha_j <- (sum_i alpha_i E_ij) * p_t[j], ascending t
#define STEPF(UU, CUR, NORM)                                                \
    {                                                                       \
        float p_;                                                           \
        if (NORM) {                                                         \
            float D_ = ws[CUR][0]; float lD_ = lg2f_(D_); loff += lD_;      \
            p_ = ex2f_(fmaf(pf[UU], LOG2E, -lD_));                          \
        } else {                                                            \
            p_ = ex2f_(pf[UU] * LOG2E);                                     \
        }                                                                   \
        pf[UU] = *(const float*)(potc + off);                               \
        off = min(off + 256, offmax);                                       \
        float s_; MAC64(&ws[CUR][0], s_);                                   \
        ws[(CUR) ^ 1][j] = s_ * p_;                                         \
        __syncthreads();                                                    \
    }

// backward: y = p_t * x; store; x <- E y, descending t
#define STEPB(UU, CUR, NORM)                                                \
    {                                                                       \
        float p_;                                                           \
        if (NORM) {                                                         \
            float D_ = ws[(CUR) ^ 1][0]; float lD_ = lg2f_(D_); loff += lD_;\
            p_ = ex2f_(fmaf(pf[UU], LOG2E, -lD_));                          \
        } else {                                                            \
            p_ = ex2f_(pf[UU] * LOG2E);                                     \
        }                                                                   \
        pf[UU] = *(const float*)(potc + off);                               \
        off = max(off - 256, offmin);                                       \
        ws[CUR][j] = p_ * x;                                                \
        __syncthreads();                                                    \
        MAC64(&ws[CUR][0], x);                                              \
    }

// One CTA per (batch, task). 64 threads, one state each.
__global__ __launch_bounds__(64, 1) void crf_chunk_kernel(
    const float* __restrict__ pot,     // [B, T, 64]
    const int*   __restrict__ seqlen,  // [B]
    const float* __restrict__ K,       // [64, 64]
    int T)
{
    const int b = blockIdx.x / NTASK;
    const int k = blockIdx.x % NTASK;
    const int j = threadIdx.x;

    int L = seqlen[b];
    if (L > T) L = T;
    if (L < 1) L = 1;
    const int M  = L - 1;                       // number of factors
    const int nc = (M + CHUNK - 1) / CHUNK;     // 0 if M==0

    const bool is_q = (k < 4);
    const int  c    = is_q ? (k + 1) : (k - 3);
    const bool valid = is_q ? (c <= nc) : (c <= nc - 1);
    if (!valid) return;

    const int a    = (c - 1) * CHUNK + 1;
    const int bend = min(c * CHUNK, M);
    const int ns   = bend - a + 1;              // >= 1

    __shared__ __align__(16) float ws[2][64];

    const float* potb = pot + (size_t)b * T * 64;
    const char*  potc = (const char*)potb;

    // ---- E registers ----
    unsigned long long e2[32];
    if (is_q) {
        // backward: row j of E -> contiguous
#pragma unroll
        for (int m = 0; m < 32; m++)
            e2[m] = pack2_(ex2f_(K[j * 64 + 2 * m]     * LOG2E),
                           ex2f_(K[j * 64 + 2 * m + 1] * LOG2E));
    } else {
        // forward: column j of E
#pragma unroll
        for (int m = 0; m < 32; m++)
            e2[m] = pack2_(ex2f_(K[(2 * m) * 64 + j]     * LOG2E),
                           ex2f_(K[(2 * m + 1) * 64 + j] * LOG2E));
    }

    float loff = 0.f;
    float pf[4];

    if (is_q) {
        // ======== backward task: x = Pi_{t=a..bend} (E diag p_t) * 1 ========
        float x = 1.0f;
#pragma unroll
        for (int u = 0; u < 4; u++) {
            int r = bend - u; if (r < a) r = a;
            pf[u] = potb[(size_t)r * 64 + j];
        }
        const int offmin = a * 256 + (j << 2);
        int off = (bend - 4) * 256 + (j << 2);
        if (off < offmin) off = offmin;

        int n4 = ns >> 2;
        for (int it = 0; it < n4; it++) {
            STEPB(0, 0, 0) STEPB(1, 1, 1) STEPB(2, 0, 0) STEPB(3, 1, 1)
        }
        int rem = ns & 3;
        if (rem > 0) STEPB(0, 0, 0)
        if (rem > 1) STEPB(1, 1, 1)
        if (rem > 2) STEPB(2, 0, 0)

        g_vec[b][k][j] = x;
        if (j == 0) g_loff[b][k] = loff;
    } else {
        // ======== forward task: r^T = 1^T Pi_{t=a..bend} (E diag p_t) ========
        ws[0][j] = 1.0f;
        __syncthreads();
#pragma unroll
        for (int u = 0; u < 4; u++) {
            int r = a + u; if (r > bend) r = bend;
            pf[u] = potb[(size_t)r * 64 + j];
        }
        const int offmax = bend * 256 + (j << 2);
        int off = (a + 4) * 256 + (j << 2);
        if (off > offmax) off = offmax;

        int n4 = ns >> 2;
        for (int it = 0; it < n4; it++) {
            STEPF(0, 0, 0) STEPF(1, 1, 1) STEPF(2, 0, 0) STEPF(3, 1, 1)
        }
        int rem = ns & 3;
        if (rem > 0) STEPF(0, 0, 0)
        if (rem > 1) STEPF(1, 1, 1)
        if (rem > 2) STEPF(2, 0, 0)

        g_vec[b][k][j] = ws[ns & 1][j];
        if (j == 0) g_loff[b][k] = loff;
    }
}

// Per-batch: seq-score gathers + stitch chunk results + global mean.
__global__ __launch_bounds__(128, 1) void crf_combine_kernel(
    const float* __restrict__ pot,
    const int*   __restrict__ tags,
    const int*   __restrict__ seqlen,
    const float* __restrict__ K,
    const float* __restrict__ sw,
    float*       __restrict__ out,
    int T, int B)
{
    const int b   = blockIdx.x;
    const int tid = threadIdx.x;

    __shared__ float sred[128];
    __shared__ int   stags[1024];

    int L = seqlen[b];
    if (L > T) L = T;
    if (L < 1) L = 1;
    const int M  = L - 1;
    const int nc = (M + CHUNK - 1) / CHUNK;

    const float* potb = pot  + (size_t)b * T * 64;
    const int*   tagb = tags + (size_t)b * T;

    for (int t = tid; t < T; t += 128) stags[t] = tagb[t];
    __syncthreads();

    float acc = 0.f;
    for (int t = tid; t < T; t += 128) {
        if (t < L) {
            int tg = stags[t];
            acc += __ldg(potb + (size_t)t * 64 + tg);
            if (t >= 1) acc += __ldg(K + stags[t - 1] * 64 + tg);
        }
    }
    sred[tid] = acc;
    __syncthreads();

    if (tid == 0) {
        float seqs = 0.f;
#pragma unroll
        for (int i = 0; i < 128; i++) seqs += sred[i];

        float log2A;
        if (nc == 0) {
            // L == 1: A = sum_j exp(pot0[j])
            float s = 0.f;
            for (int i = 0; i < 64; i++) s += ex2f_(potb[i] * LOG2E);
            log2A = lg2f_(s);
        } else {
            // d1 = alpha0^T q_1
            float d1 = 0.f;
            for (int i = 0; i < 64; i++)
                d1 += ex2f_(potb[i] * LOG2E) * g_vec[b][0][i];
            log2A = lg2f_(d1) + g_loff[b][0];
            for (int c = 2; c <= nc; c++) {
                const float* qc  = g_vec[b][c - 1];
                const float* rcm = g_vec[b][4 + c - 2];
                const float* qcm = g_vec[b][c - 2];
                float d = 0.f, sig = 0.f;
                for (int i = 0; i < 64; i++) {
                    d   += rcm[i] * qc[i];
                    sig += qcm[i];
                }
                log2A += lg2f_(d) + g_loff[b][4 + c - 2] + g_loff[b][c - 1]
                       - lg2f_(sig) - g_loff[b][c - 2];
            }
        }

        float log_norm = log2A * LN2;
        g_partial[b] = -(seqs - log_norm) * sw[b];
        __threadfence();
        unsigned int old = atomicAdd(&g_count, 1);
        if (old == gridDim.x - 1) {
            g_count = 0;               // reset for graph replay
            __threadfence();
            float tot = 0.f;
#pragma unroll 8
            for (int i = 0; i < B; i++) tot += g_partial[i];
            *out = tot / (float)B;
        }
    }
}

extern "C" void kernel_launch(void* const* d_in, const int* in_sizes, int n_in,
                              void* d_out, int out_size) {
    const float* pot    = (const float*)d_in[0];
    const int*   tags   = (const int*)d_in[1];
    const int*   seqlen = (const int*)d_in[2];
    const float* K      = (const float*)d_in[3];
    const float* sw     = (const float*)d_in[4];

    int B = in_sizes[2];            // sequence_length element count
    int T = in_sizes[1] / B;        // tags is [B, T]

    crf_chunk_kernel<<<B * NTASK, 64>>>(pot, seqlen, K, T);
    crf_combine_kernel<<<B, 128>>>(pot, tags, seqlen, K, sw, (float*)d_out, T, B);
}

// round 6
// speedup vs baseline: 3.5398x; 1.0821x over previous
#include <cuda_runtime.h>

#define LOG2E 1.4426950408889634f
#define LN2   0.6931471805599453f
#define CHUNK 128
#define MAXC  8          // max chunks: ceil(1023/128) = 8
#define NTASK 16         // 0..7 = q_1..q_8 (backward), 8..14 = r_1..r_7 (forward), 15 = gathers

__device__ float g_qv[1024][MAXC][64];      // q_c vectors
__device__ float g_rv[1024][MAXC - 1][64];  // r_c vectors
__device__ float g_qoff[1024][MAXC];
__device__ float g_roff[1024][MAXC - 1];
__device__ float g_seqs[1024];
__device__ float g_partial[1024];
__device__ unsigned int g_count = 0;

static __device__ __forceinline__ float ex2f_(float x) {
    float y; asm("ex2.approx.ftz.f32 %0, %1;" : "=f"(y) : "f"(x)); return y;
}
static __device__ __forceinline__ float lg2f_(float x) {
    float y; asm("lg2.approx.ftz.f32 %0, %1;" : "=f"(y) : "f"(x)); return y;
}
static __device__ __forceinline__ unsigned long long pack2_(float lo, float hi) {
    unsigned long long d;
    asm("mov.b64 %0, {%1, %2};" : "=l"(d) : "f"(lo), "f"(hi));
    return d;
}
static __device__ __forceinline__ unsigned long long fma2_(unsigned long long a,
                                                           unsigned long long b,
                                                           unsigned long long c) {
    unsigned long long d;
    asm("fma.rn.f32x2 %0, %1, %2, %3;" : "=l"(d) : "l"(a), "l"(b), "l"(c));
    return d;
}
static __device__ __forceinline__ unsigned long long addx2_(unsigned long long a,
                                                            unsigned long long b) {
    unsigned long long d;
    asm("add.rn.f32x2 %0, %1, %2;" : "=l"(d) : "l"(a), "l"(b));
    return d;
}
static __device__ __forceinline__ void unpack2_(unsigned long long v, float& lo, float& hi) {
    asm("mov.b64 {%0, %1}, %2;" : "=f"(lo), "=f"(hi) : "l"(v));
}
static __device__ __forceinline__ float wredsum_(float v) {
#pragma unroll
    for (int m = 16; m > 0; m >>= 1) v += __shfl_xor_sync(0xffffffffu, v, m);
    return v;
}

// s = sum over 64 i of e2 * BUF (32 packed FFMA2, broadcast LDS)
#define MAC64(BUF, SVAR)                                                    \
    {                                                                       \
        const ulonglong2* wv_ = (const ulonglong2*)(BUF);                   \
        unsigned long long a0_ = 0ull, a1_ = 0ull, a2_ = 0ull, a3_ = 0ull;  \
        _Pragma("unroll")                                                   \
        for (int k_ = 0; k_ < 8; k_++) {                                    \
            ulonglong2 q0_ = wv_[2 * k_];                                   \
            ulonglong2 q1_ = wv_[2 * k_ + 1];                               \
            a0_ = fma2_(q0_.x, e2[4 * k_ + 0], a0_);                        \
            a1_ = fma2_(q0_.y, e2[4 * k_ + 1], a1_);                        \
            a2_ = fma2_(q1_.x, e2[4 * k_ + 2], a2_);                        \
            a3_ = fma2_(q1_.y, e2[4 * k_ + 3], a3_);                        \
        }                                                                   \
        float lo_, hi_;                                                     \
        unpack2_(addx2_(addx2_(a0_, a2_), addx2_(a1_, a3_)), lo_, hi_);     \
        SVAR = lo_ + hi_;                                                   \
    }

// forward:  alpha_j <- (sum_i alpha_i E_ij) * p_t[j], ascending t
#define STEPF(UU, CUR, NORM)                                                \
    {                                                                       \
        float p_;                                                           \
        if (NORM) {                                                         \
            float D_ = ws[CUR][0]; float lD_ = lg2f_(D_); loff += lD_;      \
            p_ = ex2f_(fmaf(pf[UU], LOG2E, -lD_));                          \
        } else {                                                            \
            p_ = ex2f_(pf[UU] * LOG2E);                                     \
        }                                                                   \
        pf[UU] = *(const float*)(potc + off);                               \
        off = min(off + 256, offmax);                                       \
        float s_; MAC64(&ws[CUR][0], s_);                                   \
        ws[(CUR) ^ 1][j] = s_ * p_;                                         \
        __syncthreads();                                                    \
    }

// backward: y = p_t * x; store; x <- E y, descending t
#define STEPB(UU, CUR, NORM)                                                \
    {                                                                       \
        float p_;                                                           \
        if (NORM) {                                                         \
            float D_ = ws[(CUR) ^ 1][0]; float lD_ = lg2f_(D_); loff += lD_;\
            p_ = ex2f_(fmaf(pf[UU], LOG2E, -lD_));                          \
        } else {                                                            \
            p_ = ex2f_(pf[UU] * LOG2E);                                     \
        }                                                                   \
        pf[UU] = *(const float*)(potc + off);                               \
        off = max(off - 256, offmin);                                       \
        ws[CUR][j] = p_ * x;                                                \
        __syncthreads();                                                    \
        MAC64(&ws[CUR][0], x);                                              \
    }

// One CTA per (batch, task). 64 threads.
__global__ __launch_bounds__(64, 1) void crf_chunk_kernel(
    const float* __restrict__ pot,     // [B, T, 64]
    const int*   __restrict__ tags,    // [B, T]
    const int*   __restrict__ seqlen,  // [B]
    const float* __restrict__ K,       // [64, 64]
    int T)
{
    const int b = blockIdx.x / NTASK;
    const int k = blockIdx.x % NTASK;
    const int j = threadIdx.x;

    int L = seqlen[b];
    if (L > T) L = T;
    if (L < 1) L = 1;
    const int M  = L - 1;
    const int nc = (M + CHUNK - 1) / CHUNK;

    const float* potb = pot + (size_t)b * T * 64;
    const char*  potc = (const char*)potb;

    __shared__ __align__(16) float ws[2][64];
    __shared__ int stags[1024];
    __shared__ float sred[64];

    // ================= task 15: sequence-score gathers =================
    if (k == 15) {
        const int* tagb = tags + (size_t)b * T;
        for (int t = j; t < T; t += 64) stags[t] = tagb[t];
        __syncthreads();
        float acc = 0.f;
        for (int t = j; t < T; t += 64) {
            if (t < L) {
                int tg = stags[t];
                acc += __ldg(potb + (size_t)t * 64 + tg);
                if (t >= 1) acc += __ldg(K + stags[t - 1] * 64 + tg);
            }
        }
        sred[j] = acc;
        __syncthreads();
        if (j < 32) {
            float v = sred[j] + sred[j + 32];
            v = wredsum_(v);
            if (j == 0) g_seqs[b] = v;
        }
        return;
    }

    const bool is_q = (k < MAXC);
    const int  c    = is_q ? (k + 1) : (k - MAXC + 1);
    const bool valid = is_q ? (c <= nc) : (c <= nc - 1);
    if (!valid) return;

    const int a    = (c - 1) * CHUNK + 1;
    const int bend = min(c * CHUNK, M);
    const int ns   = bend - a + 1;

    // ---- E registers ----
    unsigned long long e2[32];
    if (is_q) {
#pragma unroll
        for (int m = 0; m < 32; m++)
            e2[m] = pack2_(ex2f_(K[j * 64 + 2 * m]     * LOG2E),
                           ex2f_(K[j * 64 + 2 * m + 1] * LOG2E));
    } else {
#pragma unroll
        for (int m = 0; m < 32; m++)
            e2[m] = pack2_(ex2f_(K[(2 * m) * 64 + j]     * LOG2E),
                           ex2f_(K[(2 * m + 1) * 64 + j] * LOG2E));
    }

    float loff = 0.f;
    float pf[4];

    if (is_q) {
        // ---- backward: x = Pi_{t=a..bend} (E diag p_t) * 1 ----
        float x = 1.0f;
#pragma unroll
        for (int u = 0; u < 4; u++) {
            int r = bend - u; if (r < a) r = a;
            pf[u] = potb[(size_t)r * 64 + j];
        }
        const int offmin = a * 256 + (j << 2);
        int off = (bend - 4) * 256 + (j << 2);
        if (off < offmin) off = offmin;

        int n4 = ns >> 2;
        for (int it = 0; it < n4; it++) {
            STEPB(0, 0, 0) STEPB(1, 1, 1) STEPB(2, 0, 0) STEPB(3, 1, 1)
        }
        int rem = ns & 3;
        if (rem > 0) STEPB(0, 0, 0)
        if (rem > 1) STEPB(1, 1, 1)
        if (rem > 2) STEPB(2, 0, 0)

        g_qv[b][c - 1][j] = x;
        if (j == 0) g_qoff[b][c - 1] = loff;
    } else {
        // ---- forward: r^T = 1^T Pi_{t=a..bend} (E diag p_t) ----
        ws[0][j] = 1.0f;
        __syncthreads();
#pragma unroll
        for (int u = 0; u < 4; u++) {
            int r = a + u; if (r > bend) r = bend;
            pf[u] = potb[(size_t)r * 64 + j];
        }
        const int offmax = bend * 256 + (j << 2);
        int off = (a + 4) * 256 + (j << 2);
        if (off > offmax) off = offmax;

        int n4 = ns >> 2;
        for (int it = 0; it < n4; it++) {
            STEPF(0, 0, 0) STEPF(1, 1, 1) STEPF(2, 0, 0) STEPF(3, 1, 1)
        }
        int rem = ns & 3;
        if (rem > 0) STEPF(0, 0, 0)
        if (rem > 1) STEPF(1, 1, 1)
        if (rem > 2) STEPF(2, 0, 0)

        g_rv[b][c - 1][j] = ws[ns & 1][j];
        if (j == 0) g_roff[b][c - 1] = loff;
    }
}

// One WARP per batch: stitch chunk results, then parallel global mean.
__global__ __launch_bounds__(32, 1) void crf_combine_kernel(
    const float* __restrict__ pot,
    const int*   __restrict__ seqlen,
    const float* __restrict__ sw,
    float*       __restrict__ out,
    int T, int B)
{
    const int b    = blockIdx.x;
    const int lane = threadIdx.x;

    int L = seqlen[b];
    if (L > T) L = T;
    if (L < 1) L = 1;
    const int M  = L - 1;
    const int nc = (M + CHUNK - 1) / CHUNK;

    const float* potb = pot + (size_t)b * T * 64;

    // prefetch everything with full MLP: lane handles states (lane, lane+32)
    float p0lo = ex2f_(potb[lane] * LOG2E);
    float p0hi = ex2f_(potb[lane + 32] * LOG2E);

    float qlo[MAXC], qhi[MAXC], rlo[MAXC - 1], rhi[MAXC - 1];
#pragma unroll
    for (int cc = 0; cc < MAXC; cc++) {
        if (cc < nc) {
            qlo[cc] = g_qv[b][cc][lane];
            qhi[cc] = g_qv[b][cc][lane + 32];
        }
    }
#pragma unroll
    for (int cc = 0; cc < MAXC - 1; cc++) {
        if (cc < nc - 1) {
            rlo[cc] = g_rv[b][cc][lane];
            rhi[cc] = g_rv[b][cc][lane + 32];
        }
    }

    float log2A;
    if (nc == 0) {
        float s = wredsum_(p0lo + p0hi);
        log2A = lg2f_(s);
    } else {
        float d1 = wredsum_(p0lo * qlo[0] + p0hi * qhi[0]);
        log2A = lg2f_(d1) + g_qoff[b][0];
        for (int cc = 2; cc <= nc; cc++) {
            float d   = wredsum_(rlo[cc - 2] * qlo[cc - 1] + rhi[cc - 2] * qhi[cc - 1]);
            float sig = wredsum_(qlo[cc - 2] + qhi[cc - 2]);
            log2A += lg2f_(d) + g_roff[b][cc - 2] + g_qoff[b][cc - 1]
                   - lg2f_(sig) - g_qoff[b][cc - 2];
        }
    }

    if (lane == 0) {
        float log_norm = log2A * LN2;
        g_partial[b] = -(g_seqs[b] - log_norm) * sw[b];
    }
    __syncwarp();
    if (lane == 0) __threadfence();
    __syncwarp();

    unsigned int old = 0;
    if (lane == 0) old = atomicAdd(&g_count, 1);
    old = __shfl_sync(0xffffffffu, old, 0);
    if (old == gridDim.x - 1) {
        if (lane == 0) { g_count = 0; __threadfence(); }
        __syncwarp();
        float tot = 0.f;
        for (int i = lane; i < B; i += 32) tot += g_partial[i];
        tot = wredsum_(tot);
        if (lane == 0) *out = tot / (float)B;
    }
}

extern "C" void kernel_launch(void* const* d_in, const int* in_sizes, int n_in,
                              void* d_out, int out_size) {
    const float* pot    = (const float*)d_in[0];
    const int*   tags   = (const int*)d_in[1];
    const int*   seqlen = (const int*)d_in[2];
    const float* K      = (const float*)d_in[3];
    const float* sw     = (const float*)d_in[4];

    int B = in_sizes[2];            // sequence_length element count
    int T = in_sizes[1] / B;        // tags is [B, T]

    crf_chunk_kernel<<<B * NTASK, 64>>>(pot, tags, seqlen, K, T);
    crf_combine_kernel<<<B, 32>>>(pot, seqlen, sw, (float*)d_out, T, B);
}